// round 15
// baseline (speedup 1.0000x reference)
#include <cuda_runtime.h>
#include <cstdint>

typedef unsigned long long ull;

#define BB   128
#define D0   2048
#define NH1  2048
#define DOUT 512
#define MAXM (100 * BB)
#define KB   16
#define ASTR 260   // duplicated-A smem row stride (floats), 8B-aligned float2 slots

// ---------------- scratch (static device globals; no allocation) --------------
__device__ float g_cur [(size_t)MAXM * NH1];   // reused: CUR0 then CUR1
__device__ float g_cur2[(size_t)MAXM * DOUT];
__device__ float g_w0t[(size_t)D0 * NH1];      // W0^T  [k][n]
__device__ float g_w1t[(size_t)NH1 * NH1];     // W1^T  [k][n]
__device__ float g_w2t[(size_t)NH1 * DOUT];    // W2^T  [k][n]

// ---------------- packed fp32 helpers (Blackwell FFMA2 path) ------------------
__device__ __forceinline__ void fma2(ull& d, ull a, ull b) {
    asm("fma.rn.f32x2 %0, %1, %2, %0;" : "+l"(d) : "l"(a), "l"(b));
}
__device__ __forceinline__ ull add2v(ull a, ull b) {
    ull d;
    asm("add.rn.f32x2 %0, %1, %2;" : "=l"(d) : "l"(a), "l"(b));
    return d;
}

// ---------------- W transpose (pure copy; values bit-identical) ---------------
__global__ void transpose_w(int id, const float* __restrict__ S, int R, int C) {
    __shared__ float t[32][33];
    float* D = (id == 0) ? g_w0t : ((id == 1) ? g_w1t : g_w2t);
    const int bx = blockIdx.x * 32, by = blockIdx.y * 32;
    const int x = threadIdx.x, y = threadIdx.y;        // 32 x 8
    #pragma unroll
    for (int j = 0; j < 32; j += 8)
        t[y + j][x] = S[(size_t)(by + y + j) * C + bx + x];
    __syncthreads();
    #pragma unroll
    for (int j = 0; j < 32; j += 8)
        D[(size_t)(bx + y + j) * R + by + x] = t[x][y + j];
}

// ================== reference-exact split-K SGEMM =============================
// C[r, n] = sum_k A[r,k] * W[n,k] in the verified reference order:
//   4 contiguous K-chunks; ascending fp32 FMA chain inside each chunk;
//   chunk sums combined ascending. fma.rn.f32x2 = two independent exact fp32
//   FMAs -> bit-faithful output (rel_err 0.0 measured R8/R10-R13).
// Block tile 128x128, 256 threads, thread tile 8x8; chunk totals in SMEM;
// 2 CTAs/SM. A stored DUPLICATED in smem (float2{v,v}) so the FFMA2 a-operand
// pairs come straight from LDS.128 broadcasts -> zero MOV dups in the mainloop
// (issue-slot relief: ~52 -> ~38 instrs per kk). B tiles are straight K-major
// cp.async copies from pre-transposed W (no STS, no conflicts, no registers).
// mode 0: A row r maps to x[b = r%128][t = r/128][k]; else A row-major.
__global__ __launch_bounds__(256, 2) void sgemm(
        int mode, int N, int K, int Tfull, const float* __restrict__ A) {
    __shared__ float As[2][KB][ASTR];  // duplicated A: 33.3 KB
    __shared__ float Bs[2][KB][128];   // 16 KB
    extern __shared__ ull tots[];      // [32][256] = 64 KB chunk totals

    const float* Bt = (mode == 0) ? g_w0t : ((mode == 1) ? g_w1t : g_w2t);
    float* C = (mode == 2) ? g_cur2 : g_cur;

    const int tid = threadIdx.x;
    const int tx = tid & 15, ty = tid >> 4;
    const int bm = blockIdx.y * 128, bn = blockIdx.x * 128;

    // ---- A prefetch coords: u in {tid, tid+256}: row = u>>2, q = u&3 ----
    size_t baseA[2];
    int rA[2], qq[2];
    #pragma unroll
    for (int i = 0; i < 2; i++) {
        int u = tid + i * 256;
        int r = u >> 2;
        qq[i] = u & 3;
        rA[i] = r;
        int row = bm + r;
        if (mode == 0) {
            int b = row & (BB - 1);
            int t = row >> 7;
            baseA[i] = ((size_t)b * Tfull + t) * (size_t)K;
        } else {
            baseA[i] = (size_t)row * K;
        }
    }

    float4 pa[2];
    auto ldg_A = [&](int kt) {
        #pragma unroll
        for (int i = 0; i < 2; i++)
            pa[i] = *(const float4*)(A + baseA[i] + kt * KB + qq[i] * 4);
    };
    auto sts_A = [&](int s) {   // duplicated store: one float2{v,v} per value
        #pragma unroll
        for (int i = 0; i < 2; i++) {
            const float va[4] = {pa[i].x, pa[i].y, pa[i].z, pa[i].w};
            #pragma unroll
            for (int j = 0; j < 4; j++)
                *(float2*)&As[s][qq[i] * 4 + j][2 * rA[i]] =
                    make_float2(va[j], va[j]);
        }
    };
    // B: straight K-major copy, 2 x 16B cp.async per thread (coalesced 512B/warp)
    auto cpa_B = [&](int kt, int s) {
        #pragma unroll
        for (int i = 0; i < 2; i++) {
            int u = tid + i * 256;
            int kl = u >> 5, c16 = u & 31;
            uint32_t dst = (uint32_t)__cvta_generic_to_shared(&Bs[s][kl][c16 * 4]);
            const float* src = Bt + (size_t)(kt * KB + kl) * N + bn + c16 * 4;
            asm volatile("cp.async.cg.shared.global [%0], [%1], 16;"
                         :: "r"(dst), "l"(src));
        }
        asm volatile("cp.async.commit_group;" ::: "memory");
    };

    ull acc[8][4];
    #pragma unroll
    for (int i = 0; i < 8; i++)
        #pragma unroll
        for (int j = 0; j < 4; j++) acc[i][j] = 0ull;

    const int nkt = K / KB;          // k-tiles; chunk = nkt/4
    const int ctile = nkt >> 2;

    cpa_B(0, 0);
    ldg_A(0);
    sts_A(0);
    asm volatile("cp.async.wait_group 0;" ::: "memory");
    __syncthreads();

    int buf = 0;
    for (int kt = 0; kt < nkt; kt++) {
        if (kt + 1 < nkt) {
            cpa_B(kt + 1, buf ^ 1);
            ldg_A(kt + 1);
        }

        #pragma unroll
        for (int kk = 0; kk < KB; kk++) {
            // a-pairs directly from duplicated smem (broadcast LDS.128)
            const ulonglong2 aw0 = *(const ulonglong2*)&As[buf][kk][ty * 8];
            const ulonglong2 aw1 = *(const ulonglong2*)&As[buf][kk][ty * 8 + 4];
            const ulonglong2 aw2 = *(const ulonglong2*)&As[buf][kk][128 + ty * 8];
            const ulonglong2 aw3 = *(const ulonglong2*)&As[buf][kk][128 + ty * 8 + 4];
            const ulonglong2 bv0 = *(const ulonglong2*)&Bs[buf][kk][tx * 4];
            const ulonglong2 bv1 = *(const ulonglong2*)&Bs[buf][kk][64 + tx * 4];
            const ull a[8] = {aw0.x, aw0.y, aw1.x, aw1.y,
                              aw2.x, aw2.y, aw3.x, aw3.y};
            const ull b[4] = {bv0.x, bv0.y, bv1.x, bv1.y};
            #pragma unroll
            for (int i = 0; i < 8; i++)
                #pragma unroll
                for (int j = 0; j < 4; j++)
                    fma2(acc[i][j], a[i], b[j]);   // ascending-k chain
        }

        if (kt + 1 < nkt) {
            sts_A(buf ^ 1);
            asm volatile("cp.async.wait_group 0;" ::: "memory");
            __syncthreads();
        }

        if (((kt + 1) & (ctile - 1)) == 0) {       // chunk boundary
            const bool first = (kt + 1) == ctile;
            #pragma unroll
            for (int i = 0; i < 8; i++)
                #pragma unroll
                for (int j = 0; j < 4; j++) {
                    ull* slot = &tots[(i * 4 + j) * 256 + tid];
                    *slot = first ? acc[i][j]
                                  : add2v(*slot, acc[i][j]);  // ascending combine
                    acc[i][j] = 0ull;
                }
        }
        buf ^= 1;
    }

    // ---- epilogue: write chunk totals (smem) to C ----
    #pragma unroll
    for (int i = 0; i < 8; i++) {
        int row = bm + ((i < 4) ? (ty * 4 + i) : (64 + ty * 4 + (i - 4)));
        float* cr = C + (size_t)row * N + bn;
        #pragma unroll
        for (int j = 0; j < 4; j++) {
            int col = (j < 2) ? (tx * 4 + j * 2) : (64 + tx * 4 + (j - 2) * 2);
            *(ull*)(cr + col) = tots[(i * 4 + j) * 256 + tid];
        }
    }
}

// ---------------- LIF time scan (bit-faithful; float2 vectorized) -------------
__global__ void scan_kernel(int layer, int T, const float* __restrict__ thp,
                            float* __restrict__ spk_rec, float* __restrict__ mem_rec) {
    const int H  = (layer == 2) ? DOUT : NH1;
    const int BH = BB * H;
    int p = blockIdx.x * blockDim.x + threadIdx.x;
    if (p >= (BH >> 1)) return;
    const int i = p << 1;
    const float* cur = (layer == 2) ? g_cur2 : g_cur;
    const float th = *thp;
    float m0 = 0.0f, m1 = 0.0f;
    for (int t = 0; t < T; t++) {
        size_t off = (size_t)t * BH + i;
        float2 c = *(const float2*)(cur + off);
        float r0 = (m0 - th > 0.0f) ? th : 0.0f;   // reset from PREVIOUS mem
        float r1 = (m1 - th > 0.0f) ? th : 0.0f;
        m0 = 0.5f * m0 + c.x - r0;
        m1 = 0.5f * m1 + c.y - r1;
        float s0 = (m0 - th > 0.0f) ? 1.0f : 0.0f;
        float s1 = (m1 - th > 0.0f) ? 1.0f : 0.0f;
        *(float2*)(mem_rec + off) = make_float2(m0, m1);
        *(float2*)(spk_rec + off) = make_float2(s0, s1);
    }
}

// ---------------- launch ----------------
extern "C" void kernel_launch(void* const* d_in, const int* in_sizes, int n_in,
                              void* d_out, int out_size) {
    const float* x   = (const float*)d_in[0];
    const float* W0  = (const float*)d_in[1];
    const float* W1  = (const float*)d_in[2];
    const float* W2  = (const float*)d_in[3];
    const float* th0 = (const float*)d_in[4];
    const float* th1 = (const float*)d_in[5];
    const float* th2 = (const float*)d_in[6];
    float* out = (float*)d_out;

    const int Tfull = in_sizes[0] / (BB * D0);
    const int T = out_size / (BB * (2 * NH1 + 2 * NH1 + 2 * DOUT));
    const int M = T * BB;

    const size_t S1 = (size_t)T * BB * NH1;
    const size_t S2 = (size_t)T * BB * DOUT;
    float* spk0 = out;
    float* spk1 = out + S1;
    float* spk2 = out + 2 * S1;
    float* mem0 = out + 2 * S1 + S2;
    float* mem1 = out + 3 * S1 + S2;
    float* mem2 = out + 4 * S1 + S2;

    const int dsm = 32 * 256 * sizeof(ull);   // 65536 B chunk-total buffer
    cudaFuncSetAttribute(sgemm, cudaFuncAttributeMaxDynamicSharedMemorySize, dsm);

    // one-time W transposes (pure copies; ~15us total)
    transpose_w<<<dim3(D0 / 32, NH1 / 32), dim3(32, 8)>>>(0, W0, NH1, D0);
    transpose_w<<<dim3(NH1 / 32, NH1 / 32), dim3(32, 8)>>>(1, W1, NH1, NH1);
    transpose_w<<<dim3(NH1 / 32, DOUT / 32), dim3(32, 8)>>>(2, W2, DOUT, NH1);

    dim3 g0(NH1 / 128, M / 128);
    sgemm<<<g0, 256, dsm>>>(0, NH1, D0, Tfull, x);
    scan_kernel<<<(BB * NH1 / 2 + 255) / 256, 256>>>(0, T, th0, spk0, mem0);

    dim3 g1(NH1 / 128, M / 128);
    sgemm<<<g1, 256, dsm>>>(1, NH1, NH1, Tfull, spk0);
    scan_kernel<<<(BB * NH1 / 2 + 255) / 256, 256>>>(1, T, th1, spk1, mem1);

    dim3 g2(DOUT / 128, M / 128);
    sgemm<<<g2, 256, dsm>>>(2, DOUT, NH1, Tfull, spk1);
    scan_kernel<<<(BB * DOUT / 2 + 255) / 256, 256>>>(2, T, th2, spk2, mem2);
}

// round 16
// speedup vs baseline: 1.0492x; 1.0492x over previous
#include <cuda_runtime.h>
#include <cstdint>

typedef unsigned long long ull;

#define BB   128
#define D0   2048
#define NH1  2048
#define DOUT 512
#define MAXM (100 * BB)
#define KB   16
#define STR  132   // padded smem row stride (floats); 16B-aligned, 2-way STS max

// ---------------- scratch (static device globals; no allocation) --------------
__device__ float g_cur [(size_t)MAXM * NH1];   // reused: CUR0 then CUR1
__device__ float g_cur2[(size_t)MAXM * DOUT];

// ---------------- packed fp32 helpers (Blackwell FFMA2 path) ------------------
__device__ __forceinline__ void fma2(ull& d, ull a, ull b) {
    asm("fma.rn.f32x2 %0, %1, %2, %0;" : "+l"(d) : "l"(a), "l"(b));
}
__device__ __forceinline__ ull add2v(ull a, ull b) {
    ull d;
    asm("add.rn.f32x2 %0, %1, %2;" : "=l"(d) : "l"(a), "l"(b));
    return d;
}
__device__ __forceinline__ ull dup2(float x) {
    ull d;
    asm("mov.b64 %0, {%1, %1};" : "=l"(d) : "f"(x));
    return d;
}

// ================== reference-exact split-K SGEMM =============================
// C[r, n] = sum_k A[r,k] * W[n,k] in the verified reference order:
//   4 contiguous K-chunks; ascending fp32 FMA chain inside each chunk;
//   chunk sums combined ascending. fma.rn.f32x2 = two independent exact fp32
//   FMAs -> bit-faithful output (rel_err 0.0 measured R8/R10-R15).
// Block tile 128x128, 256 threads. NEW thread tile 16m x 4n (8 m-PAIRS x 4 n):
//   FFMA2 lanes carry (m, m+1) -> a-operands are NATURAL float2 pairs from the
//   k-major A tile (broadcast LDS.128, zero MOVs); only the 4 b-values need
//   dup2 (8 MOVs/kk vs 16). Per-kk stream drops ~54 -> ~45 instrs.
// Chunk totals in SMEM; 2 CTAs/SM.
// mode 0: A row r maps to x[b = r%128][t = r/128][k]; else A row-major.
__global__ __launch_bounds__(256, 2) void sgemm(
        int mode, int N, int K, int Tfull,
        const float* __restrict__ A, const float* __restrict__ W) {
    __shared__ float As[2][KB][STR];   // 16.9 KB
    __shared__ float Bs[2][KB][STR];   // 16.9 KB
    extern __shared__ ull tots[];      // [32][256] = 64 KB chunk totals

    float* C = (mode == 2) ? g_cur2 : g_cur;

    const int tid = threadIdx.x;
    const int tx = tid & 31, ty = tid >> 5;   // 32 n-groups x 8 m-groups
    const int bm = blockIdx.y * 128, bn = blockIdx.x * 128;

    // ---- gmem prefetch coords: u in {tid, tid+256}: row = u>>2, q = u&3 ----
    size_t baseA[2], baseB[2];
    int rA[2], qq[2];
    #pragma unroll
    for (int i = 0; i < 2; i++) {
        int u = tid + i * 256;
        int r = u >> 2;
        qq[i] = u & 3;
        rA[i] = r;
        int row = bm + r;
        if (mode == 0) {
            int b = row & (BB - 1);
            int t = row >> 7;
            baseA[i] = ((size_t)b * Tfull + t) * (size_t)K;
        } else {
            baseA[i] = (size_t)row * K;
        }
        baseB[i] = (size_t)(bn + r) * K;
    }

    float4 pa[2], pb[2];
    auto ldg_tile = [&](int kt) {
        #pragma unroll
        for (int i = 0; i < 2; i++) {
            pa[i] = *(const float4*)(A + baseA[i] + kt * KB + qq[i] * 4);
            pb[i] = *(const float4*)(W + baseB[i] + kt * KB + qq[i] * 4);
        }
    };
    auto sts_tile = [&](int s) {
        #pragma unroll
        for (int i = 0; i < 2; i++) {
            const float va[4] = {pa[i].x, pa[i].y, pa[i].z, pa[i].w};
            const float vb[4] = {pb[i].x, pb[i].y, pb[i].z, pb[i].w};
            #pragma unroll
            for (int j = 0; j < 4; j++) {
                int kl = qq[i] * 4 + j;
                As[s][kl][rA[i]] = va[j];
                Bs[s][kl][rA[i]] = vb[j];
            }
        }
    };

    ull acc[8][4];                    // [m-pair][n]
    #pragma unroll
    for (int p = 0; p < 8; p++)
        #pragma unroll
        for (int j = 0; j < 4; j++) acc[p][j] = 0ull;

    const int nkt = K / KB;          // 128 k-tiles; chunk = 32 tiles
    const int ctile = nkt >> 2;

    ldg_tile(0);
    sts_tile(0);
    __syncthreads();

    int buf = 0;
    for (int kt = 0; kt < nkt; kt++) {
        if (kt + 1 < nkt) ldg_tile(kt + 1);

        #pragma unroll
        for (int kk = 0; kk < KB; kk++) {
            // 16 consecutive m-values: natural (m, m+1) FFMA2 pairs, broadcast
            const ulonglong2 aw0 = *(const ulonglong2*)&As[buf][kk][ty * 16];
            const ulonglong2 aw1 = *(const ulonglong2*)&As[buf][kk][ty * 16 + 4];
            const ulonglong2 aw2 = *(const ulonglong2*)&As[buf][kk][ty * 16 + 8];
            const ulonglong2 aw3 = *(const ulonglong2*)&As[buf][kk][ty * 16 + 12];
            const float4 bf = *(const float4*)&Bs[buf][kk][tx * 4];
            const ull a[8] = {aw0.x, aw0.y, aw1.x, aw1.y,
                              aw2.x, aw2.y, aw3.x, aw3.y};
            ull b[4];
            b[0] = dup2(bf.x); b[1] = dup2(bf.y);
            b[2] = dup2(bf.z); b[3] = dup2(bf.w);
            #pragma unroll
            for (int p = 0; p < 8; p++)
                #pragma unroll
                for (int j = 0; j < 4; j++)
                    fma2(acc[p][j], a[p], b[j]);   // ascending-k chain
        }

        if (kt + 1 < nkt) {
            sts_tile(buf ^ 1);
            __syncthreads();
        }

        if (((kt + 1) & (ctile - 1)) == 0) {       // chunk boundary
            const bool first = (kt + 1) == ctile;
            #pragma unroll
            for (int p = 0; p < 8; p++)
                #pragma unroll
                for (int j = 0; j < 4; j++) {
                    ull* slot = &tots[(p * 4 + j) * 256 + tid];
                    *slot = first ? acc[p][j]
                                  : add2v(*slot, acc[p][j]);  // ascending combine
                    acc[p][j] = 0ull;
                }
        }
        buf ^= 1;
    }

    // ---- epilogue: unpack (m, m+1) pairs, coalesced float4 stores ----
    #pragma unroll
    for (int p = 0; p < 8; p++) {
        float2 t[4];
        #pragma unroll
        for (int j = 0; j < 4; j++) {
            ull v = tots[(p * 4 + j) * 256 + tid];
            t[j] = *(float2*)&v;
        }
        const int row0 = bm + ty * 16 + 2 * p;
        float* c0 = C + (size_t)row0 * N + bn + tx * 4;
        float* c1 = c0 + N;
        *(float4*)c0 = make_float4(t[0].x, t[1].x, t[2].x, t[3].x);
        *(float4*)c1 = make_float4(t[0].y, t[1].y, t[2].y, t[3].y);
    }
}

// ---------------- LIF time scan (bit-faithful; float2 vectorized) -------------
__global__ void scan_kernel(int layer, int T, const float* __restrict__ thp,
                            float* __restrict__ spk_rec, float* __restrict__ mem_rec) {
    const int H  = (layer == 2) ? DOUT : NH1;
    const int BH = BB * H;
    int p = blockIdx.x * blockDim.x + threadIdx.x;
    if (p >= (BH >> 1)) return;
    const int i = p << 1;
    const float* cur = (layer == 2) ? g_cur2 : g_cur;
    const float th = *thp;
    float m0 = 0.0f, m1 = 0.0f;
    for (int t = 0; t < T; t++) {
        size_t off = (size_t)t * BH + i;
        float2 c = *(const float2*)(cur + off);
        float r0 = (m0 - th > 0.0f) ? th : 0.0f;   // reset from PREVIOUS mem
        float r1 = (m1 - th > 0.0f) ? th : 0.0f;
        m0 = 0.5f * m0 + c.x - r0;
        m1 = 0.5f * m1 + c.y - r1;
        float s0 = (m0 - th > 0.0f) ? 1.0f : 0.0f;
        float s1 = (m1 - th > 0.0f) ? 1.0f : 0.0f;
        *(float2*)(mem_rec + off) = make_float2(m0, m1);
        *(float2*)(spk_rec + off) = make_float2(s0, s1);
    }
}

// ---------------- launch ----------------
extern "C" void kernel_launch(void* const* d_in, const int* in_sizes, int n_in,
                              void* d_out, int out_size) {
    const float* x   = (const float*)d_in[0];
    const float* W0  = (const float*)d_in[1];
    const float* W1  = (const float*)d_in[2];
    const float* W2  = (const float*)d_in[3];
    const float* th0 = (const float*)d_in[4];
    const float* th1 = (const float*)d_in[5];
    const float* th2 = (const float*)d_in[6];
    float* out = (float*)d_out;

    const int Tfull = in_sizes[0] / (BB * D0);
    const int T = out_size / (BB * (2 * NH1 + 2 * NH1 + 2 * DOUT));
    const int M = T * BB;

    const size_t S1 = (size_t)T * BB * NH1;
    const size_t S2 = (size_t)T * BB * DOUT;
    float* spk0 = out;
    float* spk1 = out + S1;
    float* spk2 = out + 2 * S1;
    float* mem0 = out + 2 * S1 + S2;
    float* mem1 = out + 3 * S1 + S2;
    float* mem2 = out + 4 * S1 + S2;

    const int dsm = 32 * 256 * sizeof(ull);   // 65536 B chunk-total buffer
    cudaFuncSetAttribute(sgemm, cudaFuncAttributeMaxDynamicSharedMemorySize, dsm);

    dim3 g0(NH1 / 128, M / 128);
    sgemm<<<g0, 256, dsm>>>(0, NH1, D0, Tfull, x, W0);
    scan_kernel<<<(BB * NH1 / 2 + 255) / 256, 256>>>(0, T, th0, spk0, mem0);

    dim3 g1(NH1 / 128, M / 128);
    sgemm<<<g1, 256, dsm>>>(1, NH1, NH1, Tfull, spk0, W1);
    scan_kernel<<<(BB * NH1 / 2 + 255) / 256, 256>>>(1, T, th1, spk1, mem1);

    dim3 g2(DOUT / 128, M / 128);
    sgemm<<<g2, 256, dsm>>>(2, DOUT, NH1, Tfull, spk1, W2);
    scan_kernel<<<(BB * DOUT / 2 + 255) / 256, 256>>>(2, T, th2, spk2, mem2);
}

// round 17
// speedup vs baseline: 1.2436x; 1.1852x over previous
#include <cuda_runtime.h>
#include <cstdint>

typedef unsigned long long ull;

#define BB   128
#define D0   2048
#define NH1  2048
#define DOUT 512
#define MAXM (100 * BB)
#define KB   16
#define STR  132   // padded smem row stride (floats): kills 4-way STS conflicts,
                   // keeps 16B alignment for float4/ulonglong2 mainloop reads

// ---------------- scratch (static device globals; no allocation) --------------
__device__ float g_cur [(size_t)MAXM * NH1];   // reused: CUR0 then CUR1
__device__ float g_cur2[(size_t)MAXM * DOUT];

// ---------------- packed fp32 helpers (Blackwell FFMA2 path) ------------------
__device__ __forceinline__ void fma2(ull& d, ull a, ull b) {
    asm("fma.rn.f32x2 %0, %1, %2, %0;" : "+l"(d) : "l"(a), "l"(b));
}
__device__ __forceinline__ ull add2v(ull a, ull b) {
    ull d;
    asm("add.rn.f32x2 %0, %1, %2;" : "=l"(d) : "l"(a), "l"(b));
    return d;
}
__device__ __forceinline__ ull dup2(float x) {
    ull d;
    asm("mov.b64 %0, {%1, %1};" : "=l"(d) : "f"(x));
    return d;
}

// ================== reference-exact split-K SGEMM (R12 config) ================
// C[r, n] = sum_k A[r,k] * W[n,k] in the verified reference order:
//   4 contiguous K-chunks; ascending fp32 FMA chain inside each chunk;
//   chunk sums combined ascending. fma.rn.f32x2 = two independent exact fp32
//   FMAs -> bit-faithful output (rel_err 0.0 measured R8/R10-R16).
// Block tile 128x128, 256 threads, thread tile 8x8; chunk totals in SMEM;
// 2 CTAs/SM. This is the best-measured configuration (4305us, fma pipe 72.8%).
// mode 0: A row r maps to x[b = r%128][t = r/128][k]; else A row-major.
__global__ __launch_bounds__(256, 2) void sgemm(
        int mode, int N, int K, int Tfull,
        const float* __restrict__ A, const float* __restrict__ W) {
    __shared__ float As[2][KB][STR];   // 16.9 KB
    __shared__ float Bs[2][KB][STR];   // 16.9 KB
    extern __shared__ ull tots[];      // [32][256] = 64 KB chunk totals

    float* C = (mode == 2) ? g_cur2 : g_cur;

    const int tid = threadIdx.x;
    const int tx = tid & 15, ty = tid >> 4;
    const int bm = blockIdx.y * 128, bn = blockIdx.x * 128;

    // ---- gmem prefetch coords: u in {tid, tid+256}: row = u>>2, q = u&3 ----
    size_t baseA[2], baseB[2];
    int rA[2], qq[2];
    #pragma unroll
    for (int i = 0; i < 2; i++) {
        int u = tid + i * 256;
        int r = u >> 2;
        qq[i] = u & 3;
        rA[i] = r;
        int row = bm + r;
        if (mode == 0) {
            int b = row & (BB - 1);
            int t = row >> 7;
            baseA[i] = ((size_t)b * Tfull + t) * (size_t)K;
        } else {
            baseA[i] = (size_t)row * K;
        }
        baseB[i] = (size_t)(bn + r) * K;
    }

    float4 pa[2], pb[2];
    auto ldg_tile = [&](int kt) {
        #pragma unroll
        for (int i = 0; i < 2; i++) {
            pa[i] = *(const float4*)(A + baseA[i] + kt * KB + qq[i] * 4);
            pb[i] = *(const float4*)(W + baseB[i] + kt * KB + qq[i] * 4);
        }
    };
    auto sts_tile = [&](int s) {
        #pragma unroll
        for (int i = 0; i < 2; i++) {
            const float va[4] = {pa[i].x, pa[i].y, pa[i].z, pa[i].w};
            const float vb[4] = {pb[i].x, pb[i].y, pb[i].z, pb[i].w};
            #pragma unroll
            for (int j = 0; j < 4; j++) {
                int kl = qq[i] * 4 + j;
                As[s][kl][rA[i]] = va[j];
                Bs[s][kl][rA[i]] = vb[j];
            }
        }
    };

    ull acc[8][4];
    #pragma unroll
    for (int i = 0; i < 8; i++)
        #pragma unroll
        for (int j = 0; j < 4; j++) acc[i][j] = 0ull;

    const int nkt = K / KB;          // 128 k-tiles; chunk = 32 tiles
    const int ctile = nkt >> 2;

    ldg_tile(0);
    sts_tile(0);
    __syncthreads();

    int buf = 0;
    for (int kt = 0; kt < nkt; kt++) {
        if (kt + 1 < nkt) ldg_tile(kt + 1);

        #pragma unroll
        for (int kk = 0; kk < KB; kk++) {
            const float4 av0 = *(const float4*)&As[buf][kk][ty * 4];
            const float4 av1 = *(const float4*)&As[buf][kk][64 + ty * 4];
            const ulonglong2 bv0 = *(const ulonglong2*)&Bs[buf][kk][tx * 4];
            const ulonglong2 bv1 = *(const ulonglong2*)&Bs[buf][kk][64 + tx * 4];
            ull a[8];
            a[0] = dup2(av0.x); a[1] = dup2(av0.y);
            a[2] = dup2(av0.z); a[3] = dup2(av0.w);
            a[4] = dup2(av1.x); a[5] = dup2(av1.y);
            a[6] = dup2(av1.z); a[7] = dup2(av1.w);
            const ull b[4] = {bv0.x, bv0.y, bv1.x, bv1.y};
            #pragma unroll
            for (int i = 0; i < 8; i++)
                #pragma unroll
                for (int j = 0; j < 4; j++)
                    fma2(acc[i][j], a[i], b[j]);   // ascending-k chain
        }

        if (kt + 1 < nkt) {
            sts_tile(buf ^ 1);
            __syncthreads();
        }

        if (((kt + 1) & (ctile - 1)) == 0) {       // chunk boundary
            const bool first = (kt + 1) == ctile;
            #pragma unroll
            for (int i = 0; i < 8; i++)
                #pragma unroll
                for (int j = 0; j < 4; j++) {
                    ull* slot = &tots[(i * 4 + j) * 256 + tid];
                    *slot = first ? acc[i][j]
                                  : add2v(*slot, acc[i][j]);  // ascending combine
                    acc[i][j] = 0ull;
                }
        }
        buf ^= 1;
    }

    // ---- epilogue: write chunk totals (smem) to C ----
    #pragma unroll
    for (int i = 0; i < 8; i++) {
        int row = bm + ((i < 4) ? (ty * 4 + i) : (64 + ty * 4 + (i - 4)));
        float* cr = C + (size_t)row * N + bn;
        #pragma unroll
        for (int j = 0; j < 4; j++) {
            int col = (j < 2) ? (tx * 4 + j * 2) : (64 + tx * 4 + (j - 2) * 2);
            *(ull*)(cr + col) = tots[(i * 4 + j) * 256 + tid];
        }
    }
}

// ---------------- LIF time scan (bit-faithful; float2 vectorized) -------------
__global__ void scan_kernel(int layer, int T, const float* __restrict__ thp,
                            float* __restrict__ spk_rec, float* __restrict__ mem_rec) {
    const int H  = (layer == 2) ? DOUT : NH1;
    const int BH = BB * H;
    int p = blockIdx.x * blockDim.x + threadIdx.x;
    if (p >= (BH >> 1)) return;
    const int i = p << 1;
    const float* cur = (layer == 2) ? g_cur2 : g_cur;
    const float th = *thp;
    float m0 = 0.0f, m1 = 0.0f;
    for (int t = 0; t < T; t++) {
        size_t off = (size_t)t * BH + i;
        float2 c = *(const float2*)(cur + off);
        float r0 = (m0 - th > 0.0f) ? th : 0.0f;   // reset from PREVIOUS mem
        float r1 = (m1 - th > 0.0f) ? th : 0.0f;
        m0 = 0.5f * m0 + c.x - r0;
        m1 = 0.5f * m1 + c.y - r1;
        float s0 = (m0 - th > 0.0f) ? 1.0f : 0.0f;
        float s1 = (m1 - th > 0.0f) ? 1.0f : 0.0f;
        *(float2*)(mem_rec + off) = make_float2(m0, m1);
        *(float2*)(spk_rec + off) = make_float2(s0, s1);
    }
}

// ---------------- launch ----------------
extern "C" void kernel_launch(void* const* d_in, const int* in_sizes, int n_in,
                              void* d_out, int out_size) {
    const float* x   = (const float*)d_in[0];
    const float* W0  = (const float*)d_in[1];
    const float* W1  = (const float*)d_in[2];
    const float* W2  = (const float*)d_in[3];
    const float* th0 = (const float*)d_in[4];
    const float* th1 = (const float*)d_in[5];
    const float* th2 = (const float*)d_in[6];
    float* out = (float*)d_out;

    const int Tfull = in_sizes[0] / (BB * D0);
    const int T = out_size / (BB * (2 * NH1 + 2 * NH1 + 2 * DOUT));
    const int M = T * BB;

    const size_t S1 = (size_t)T * BB * NH1;
    const size_t S2 = (size_t)T * BB * DOUT;
    float* spk0 = out;
    float* spk1 = out + S1;
    float* spk2 = out + 2 * S1;
    float* mem0 = out + 2 * S1 + S2;
    float* mem1 = out + 3 * S1 + S2;
    float* mem2 = out + 4 * S1 + S2;

    const int dsm = 32 * 256 * sizeof(ull);   // 65536 B chunk-total buffer
    cudaFuncSetAttribute(sgemm, cudaFuncAttributeMaxDynamicSharedMemorySize, dsm);

    dim3 g0(NH1 / 128, M / 128);
    sgemm<<<g0, 256, dsm>>>(0, NH1, D0, Tfull, x, W0);
    scan_kernel<<<(BB * NH1 / 2 + 255) / 256, 256>>>(0, T, th0, spk0, mem0);

    dim3 g1(NH1 / 128, M / 128);
    sgemm<<<g1, 256, dsm>>>(1, NH1, NH1, Tfull, spk0, W1);
    scan_kernel<<<(BB * NH1 / 2 + 255) / 256, 256>>>(1, T, th1, spk1, mem1);

    dim3 g2(DOUT / 128, M / 128);
    sgemm<<<g2, 256, dsm>>>(2, DOUT, NH1, Tfull, spk1, W2);
    scan_kernel<<<(BB * DOUT / 2 + 255) / 256, 256>>>(2, T, th2, spk2, mem2);
}